// round 1
// baseline (speedup 1.0000x reference)
#include <cuda_runtime.h>
#include <math.h>

#define T_TOK 2048
#define D_DIM 1024
#define F_DIM 4096
#define E_NUM 8
#define NPAIR (T_TOK * 2)

#define BM 128
#define BN 64
#define BK 32
#define APAD 4   // As row stride = BM+APAD = 132 floats (16B-aligned rows, bank-spread)

// ---------------- scratch (device globals: no runtime allocation) ----------------
__device__ int   g_off[E_NUM + 1];
__device__ int   g_pair_tok[NPAIR];
__device__ int   g_pair_slot[NPAIR];
__device__ float g_pair_w[NPAIR];
__device__ int   g_tok_e[NPAIR];
__device__ float g_tok_w[NPAIR];
__device__ float g_h[(size_t)NPAIR * F_DIM];   // 64 MB: silu(gate)*up per (token,slot)
__device__ float g_y[(size_t)NPAIR * D_DIM];   // 16 MB: per-(token,slot) down-proj output

// ---------------- 1) router: logits -> top2 -> renormalized weights ----------------
__global__ void router_kernel(const float* __restrict__ x, const float* __restrict__ wr) {
    int warp = threadIdx.x >> 5;
    int lane = threadIdx.x & 31;
    int t = blockIdx.x * 8 + warp;
    if (t >= T_TOK) return;

    float acc[E_NUM];
#pragma unroll
    for (int e = 0; e < E_NUM; e++) acc[e] = 0.f;

    const float* xr = x + (size_t)t * D_DIM;
    for (int d = lane; d < D_DIM; d += 32) {
        float xv = xr[d];
        const float4* w4 = (const float4*)(wr + (size_t)d * E_NUM);
        float4 w0 = w4[0];
        float4 w1 = w4[1];
        acc[0] += xv * w0.x; acc[1] += xv * w0.y;
        acc[2] += xv * w0.z; acc[3] += xv * w0.w;
        acc[4] += xv * w1.x; acc[5] += xv * w1.y;
        acc[6] += xv * w1.z; acc[7] += xv * w1.w;
    }
#pragma unroll
    for (int off = 16; off > 0; off >>= 1) {
#pragma unroll
        for (int e = 0; e < E_NUM; e++)
            acc[e] += __shfl_xor_sync(0xFFFFFFFFu, acc[e], off);
    }
    if (lane == 0) {
        // top-1 (strict > keeps lower index on ties, matching lax.top_k)
        int i1 = 0;
#pragma unroll
        for (int e = 1; e < E_NUM; e++) if (acc[e] > acc[i1]) i1 = e;
        int i2 = (i1 == 0) ? 1 : 0;
#pragma unroll
        for (int e = 0; e < E_NUM; e++)
            if (e != i1 && acc[e] > acc[i2]) i2 = e;
        // renormalized top-2 softmax weights: w1 = e^{l1}/(e^{l1}+e^{l2})
        float w1 = 1.f / (1.f + expf(acc[i2] - acc[i1]));
        g_tok_e[t * 2 + 0] = i1;
        g_tok_e[t * 2 + 1] = i2;
        g_tok_w[t * 2 + 0] = w1;
        g_tok_w[t * 2 + 1] = 1.f - w1;
    }
}

// ---------------- 2) build contiguous per-expert pair lists (single block) ----------------
__global__ void assign_kernel() {
    __shared__ int s_cnt[E_NUM];
    __shared__ int s_fill[E_NUM];
    if (threadIdx.x < E_NUM) s_cnt[threadIdx.x] = 0;
    __syncthreads();
    for (int p = threadIdx.x; p < NPAIR; p += blockDim.x)
        atomicAdd(&s_cnt[g_tok_e[p]], 1);
    __syncthreads();
    if (threadIdx.x == 0) {
        int o = 0;
        for (int e = 0; e < E_NUM; e++) {
            g_off[e] = o;
            s_fill[e] = o;
            o += s_cnt[e];
        }
        g_off[E_NUM] = o;  // == NPAIR
    }
    __syncthreads();
    for (int p = threadIdx.x; p < NPAIR; p += blockDim.x) {
        int e = g_tok_e[p];
        int pos = atomicAdd(&s_fill[e], 1);
        g_pair_tok[pos]  = p >> 1;
        g_pair_slot[pos] = p & 1;
        g_pair_w[pos]    = g_tok_w[p];
    }
}

// ---------------- 3) fused gate+up GEMM + SiLU: h[p,f] = silu(x_t . Wg) * (x_t . Wu) ----------------
__global__ void __launch_bounds__(256, 2)
gateup_kernel(const float* __restrict__ x,
              const float* __restrict__ Wg,
              const float* __restrict__ Wu) {
    int e = blockIdx.z;
    int base = g_off[e] + blockIdx.x * BM;
    int end  = g_off[e + 1];
    if (base >= end) return;
    int nb = blockIdx.y * BN;

    __shared__ float As[BK][BM + APAD];
    __shared__ float Bgs[BK][BN];
    __shared__ float Bus[BK][BN];

    const float* wg = Wg + (size_t)e * D_DIM * F_DIM;
    const float* wu = Wu + (size_t)e * D_DIM * F_DIM;

    int tid = threadIdx.x;
    int ty = tid >> 4;        // 0..15 -> 8 rows each
    int tx = tid & 15;        // 0..15 -> 4 cols each

    float accg[8][4];
    float accu[8][4];
#pragma unroll
    for (int i = 0; i < 8; i++)
#pragma unroll
        for (int j = 0; j < 4; j++) { accg[i][j] = 0.f; accu[i][j] = 0.f; }

    // A-load mapping: 128 rows x 8 float4/row = 1024 float4; 4 per thread
    int rowTok[4];
#pragma unroll
    for (int j = 0; j < 4; j++) {
        int flat = tid + j * 256;
        int row = flat >> 3;
        int p = base + row;
        rowTok[j] = (p < end) ? g_pair_tok[p] : -1;
    }

    for (int kb = 0; kb < D_DIM; kb += BK) {
        // A tile (gathered, stored K-major/transposed)
#pragma unroll
        for (int j = 0; j < 4; j++) {
            int flat = tid + j * 256;
            int row = flat >> 3;
            int c4 = flat & 7;
            float4 v = make_float4(0.f, 0.f, 0.f, 0.f);
            if (rowTok[j] >= 0)
                v = *(const float4*)(x + (size_t)rowTok[j] * D_DIM + kb + c4 * 4);
            As[c4 * 4 + 0][row] = v.x;
            As[c4 * 4 + 1][row] = v.y;
            As[c4 * 4 + 2][row] = v.z;
            As[c4 * 4 + 3][row] = v.w;
        }
        // B tiles: 32 rows x 16 float4/row = 512 float4; 2 per thread per matrix
#pragma unroll
        for (int j = 0; j < 2; j++) {
            int flat = tid + j * 256;
            int row = flat >> 4;
            int c4 = flat & 15;
            size_t off = (size_t)(kb + row) * F_DIM + nb + c4 * 4;
            *(float4*)&Bgs[row][c4 * 4] = *(const float4*)(wg + off);
            *(float4*)&Bus[row][c4 * 4] = *(const float4*)(wu + off);
        }
        __syncthreads();

#pragma unroll
        for (int kk = 0; kk < BK; kk++) {
            float a[8], bg[4], bu[4];
#pragma unroll
            for (int i = 0; i < 8; i++) a[i] = As[kk][ty * 8 + i];
#pragma unroll
            for (int j = 0; j < 4; j++) { bg[j] = Bgs[kk][tx * 4 + j]; bu[j] = Bus[kk][tx * 4 + j]; }
#pragma unroll
            for (int i = 0; i < 8; i++)
#pragma unroll
                for (int j = 0; j < 4; j++) {
                    accg[i][j] += a[i] * bg[j];
                    accu[i][j] += a[i] * bu[j];
                }
        }
        __syncthreads();
    }

    // epilogue: SiLU(gate) * up
#pragma unroll
    for (int i = 0; i < 8; i++) {
        int p = base + ty * 8 + i;
        if (p >= end) continue;
        float* hrow = g_h + (size_t)p * F_DIM + nb + tx * 4;
#pragma unroll
        for (int j = 0; j < 4; j++) {
            float g = accg[i][j];
            float s = 1.f / (1.f + expf(-g));
            hrow[j] = g * s * accu[i][j];
        }
    }
}

// ---------------- 4) down-proj GEMM: y[t,slot,:] = w * (h[p,:] @ Wd[e]) ----------------
__global__ void __launch_bounds__(256, 2)
down_kernel(const float* __restrict__ Wd) {
    int e = blockIdx.z;
    int base = g_off[e] + blockIdx.x * BM;
    int end  = g_off[e + 1];
    if (base >= end) return;
    int nb = blockIdx.y * BN;

    __shared__ float As[BK][BM + APAD];
    __shared__ float Bs[BK][BN];

    const float* wd = Wd + (size_t)e * F_DIM * D_DIM;

    int tid = threadIdx.x;
    int ty = tid >> 4;
    int tx = tid & 15;

    float acc[8][4];
#pragma unroll
    for (int i = 0; i < 8; i++)
#pragma unroll
        for (int j = 0; j < 4; j++) acc[i][j] = 0.f;

    for (int kb = 0; kb < F_DIM; kb += BK) {
#pragma unroll
        for (int j = 0; j < 4; j++) {
            int flat = tid + j * 256;
            int row = flat >> 3;
            int c4 = flat & 7;
            int p = base + row;
            float4 v = make_float4(0.f, 0.f, 0.f, 0.f);
            if (p < end)
                v = *(const float4*)(g_h + (size_t)p * F_DIM + kb + c4 * 4);
            As[c4 * 4 + 0][row] = v.x;
            As[c4 * 4 + 1][row] = v.y;
            As[c4 * 4 + 2][row] = v.z;
            As[c4 * 4 + 3][row] = v.w;
        }
#pragma unroll
        for (int j = 0; j < 2; j++) {
            int flat = tid + j * 256;
            int row = flat >> 4;
            int c4 = flat & 15;
            size_t off = (size_t)(kb + row) * D_DIM + nb + c4 * 4;
            *(float4*)&Bs[row][c4 * 4] = *(const float4*)(wd + off);
        }
        __syncthreads();

#pragma unroll
        for (int kk = 0; kk < BK; kk++) {
            float a[8], b[4];
#pragma unroll
            for (int i = 0; i < 8; i++) a[i] = As[kk][ty * 8 + i];
#pragma unroll
            for (int j = 0; j < 4; j++) b[j] = Bs[kk][tx * 4 + j];
#pragma unroll
            for (int i = 0; i < 8; i++)
#pragma unroll
                for (int j = 0; j < 4; j++) acc[i][j] += a[i] * b[j];
        }
        __syncthreads();
    }

#pragma unroll
    for (int i = 0; i < 8; i++) {
        int p = base + ty * 8 + i;
        if (p >= end) continue;
        int t = g_pair_tok[p];
        int slot = g_pair_slot[p];
        float w = g_pair_w[p];
        float* yrow = g_y + ((size_t)(t * 2 + slot)) * D_DIM + nb + tx * 4;
#pragma unroll
        for (int j = 0; j < 4; j++) yrow[j] = w * acc[i][j];
    }
}

// ---------------- 5) combine: out[t,:] = y[t,0,:] + y[t,1,:] ----------------
__global__ void combine_kernel(float* __restrict__ out) {
    int i = blockIdx.x * blockDim.x + threadIdx.x;  // 0 .. T*D-1
    if (i >= T_TOK * D_DIM) return;
    int t = i >> 10;
    int d = i & (D_DIM - 1);
    out[i] = g_y[((size_t)(t * 2) ) * D_DIM + d] + g_y[((size_t)(t * 2 + 1)) * D_DIM + d];
}

// ---------------- launch ----------------
extern "C" void kernel_launch(void* const* d_in, const int* in_sizes, int n_in,
                              void* d_out, int out_size) {
    const float* x  = (const float*)d_in[0];
    const float* wr = (const float*)d_in[1];
    const float* Wg = (const float*)d_in[2];
    const float* Wu = (const float*)d_in[3];
    const float* Wd = (const float*)d_in[4];
    float* out = (float*)d_out;

    router_kernel<<<T_TOK / 8, 256>>>(x, wr);
    assign_kernel<<<1, 256>>>();
    gateup_kernel<<<dim3(T_TOK / BM, F_DIM / BN, E_NUM), 256>>>(x, Wg, Wu);
    down_kernel<<<dim3(T_TOK / BM, D_DIM / BN, E_NUM), 256>>>(Wd);
    combine_kernel<<<(T_TOK * D_DIM + 255) / 256, 256>>>(out);
}

// round 2
// speedup vs baseline: 1.0009x; 1.0009x over previous
#include <cuda_runtime.h>
#include <math.h>

#define T_TOK 2048
#define D_DIM 1024
#define F_DIM 4096
#define E_NUM 8
#define NPAIR (T_TOK * 2)

#define BM 128
#define BN 64
#define BK 32
#define APAD 4   // As row stride = BM+APAD = 132 floats (16B-aligned rows, bank-spread)

// ---------------- scratch (device globals: no runtime allocation) ----------------
__device__ int   g_off[E_NUM + 1];
__device__ int   g_pair_tok[NPAIR];
__device__ int   g_pair_slot[NPAIR];
__device__ float g_pair_w[NPAIR];
__device__ int   g_tok_e[NPAIR];
__device__ float g_tok_w[NPAIR];
__device__ float g_h[(size_t)NPAIR * F_DIM];   // 64 MB: silu(gate)*up per (token,slot)
__device__ float g_y[(size_t)NPAIR * D_DIM];   // 16 MB: per-(token,slot) down-proj output

// ---------------- 1) router: logits -> top2 -> renormalized weights ----------------
__global__ void router_kernel(const float* __restrict__ x, const float* __restrict__ wr) {
    int warp = threadIdx.x >> 5;
    int lane = threadIdx.x & 31;
    int t = blockIdx.x * 8 + warp;
    if (t >= T_TOK) return;

    float acc[E_NUM];
#pragma unroll
    for (int e = 0; e < E_NUM; e++) acc[e] = 0.f;

    const float* xr = x + (size_t)t * D_DIM;
    for (int d = lane; d < D_DIM; d += 32) {
        float xv = xr[d];
        const float4* w4 = (const float4*)(wr + (size_t)d * E_NUM);
        float4 w0 = w4[0];
        float4 w1 = w4[1];
        acc[0] += xv * w0.x; acc[1] += xv * w0.y;
        acc[2] += xv * w0.z; acc[3] += xv * w0.w;
        acc[4] += xv * w1.x; acc[5] += xv * w1.y;
        acc[6] += xv * w1.z; acc[7] += xv * w1.w;
    }
#pragma unroll
    for (int off = 16; off > 0; off >>= 1) {
#pragma unroll
        for (int e = 0; e < E_NUM; e++)
            acc[e] += __shfl_xor_sync(0xFFFFFFFFu, acc[e], off);
    }
    if (lane == 0) {
        // top-1 (strict > keeps lower index on ties, matching lax.top_k)
        int i1 = 0;
#pragma unroll
        for (int e = 1; e < E_NUM; e++) if (acc[e] > acc[i1]) i1 = e;
        int i2 = (i1 == 0) ? 1 : 0;
#pragma unroll
        for (int e = 0; e < E_NUM; e++)
            if (e != i1 && acc[e] > acc[i2]) i2 = e;
        // renormalized top-2 softmax weights: w1 = e^{l1}/(e^{l1}+e^{l2})
        float w1 = 1.f / (1.f + expf(acc[i2] - acc[i1]));
        g_tok_e[t * 2 + 0] = i1;
        g_tok_e[t * 2 + 1] = i2;
        g_tok_w[t * 2 + 0] = w1;
        g_tok_w[t * 2 + 1] = 1.f - w1;
    }
}

// ---------------- 2) build contiguous per-expert pair lists (single block) ----------------
__global__ void assign_kernel() {
    __shared__ int s_cnt[E_NUM];
    __shared__ int s_fill[E_NUM];
    if (threadIdx.x < E_NUM) s_cnt[threadIdx.x] = 0;
    __syncthreads();
    for (int p = threadIdx.x; p < NPAIR; p += blockDim.x)
        atomicAdd(&s_cnt[g_tok_e[p]], 1);
    __syncthreads();
    if (threadIdx.x == 0) {
        int o = 0;
        for (int e = 0; e < E_NUM; e++) {
            g_off[e] = o;
            s_fill[e] = o;
            o += s_cnt[e];
        }
        g_off[E_NUM] = o;  // == NPAIR
    }
    __syncthreads();
    for (int p = threadIdx.x; p < NPAIR; p += blockDim.x) {
        int e = g_tok_e[p];
        int pos = atomicAdd(&s_fill[e], 1);
        g_pair_tok[pos]  = p >> 1;
        g_pair_slot[pos] = p & 1;
        g_pair_w[pos]    = g_tok_w[p];
    }
}

// ---------------- 3) fused gate+up GEMM + SiLU: h[p,f] = silu(x_t . Wg) * (x_t . Wu) ----------------
__global__ void __launch_bounds__(256, 2)
gateup_kernel(const float* __restrict__ x,
              const float* __restrict__ Wg,
              const float* __restrict__ Wu) {
    int e = blockIdx.z;
    int base = g_off[e] + blockIdx.x * BM;
    int end  = g_off[e + 1];
    if (base >= end) return;
    int nb = blockIdx.y * BN;

    __shared__ float As[BK][BM + APAD];
    __shared__ float Bgs[BK][BN];
    __shared__ float Bus[BK][BN];

    const float* wg = Wg + (size_t)e * D_DIM * F_DIM;
    const float* wu = Wu + (size_t)e * D_DIM * F_DIM;

    int tid = threadIdx.x;
    int ty = tid >> 4;        // 0..15 -> 8 rows each
    int tx = tid & 15;        // 0..15 -> 4 cols each

    float accg[8][4];
    float accu[8][4];
#pragma unroll
    for (int i = 0; i < 8; i++)
#pragma unroll
        for (int j = 0; j < 4; j++) { accg[i][j] = 0.f; accu[i][j] = 0.f; }

    // A-load mapping: 128 rows x 8 float4/row = 1024 float4; 4 per thread
    int rowTok[4];
#pragma unroll
    for (int j = 0; j < 4; j++) {
        int flat = tid + j * 256;
        int row = flat >> 3;
        int p = base + row;
        rowTok[j] = (p < end) ? g_pair_tok[p] : -1;
    }

    for (int kb = 0; kb < D_DIM; kb += BK) {
        // A tile (gathered, stored K-major/transposed)
#pragma unroll
        for (int j = 0; j < 4; j++) {
            int flat = tid + j * 256;
            int row = flat >> 3;
            int c4 = flat & 7;
            float4 v = make_float4(0.f, 0.f, 0.f, 0.f);
            if (rowTok[j] >= 0)
                v = *(const float4*)(x + (size_t)rowTok[j] * D_DIM + kb + c4 * 4);
            As[c4 * 4 + 0][row] = v.x;
            As[c4 * 4 + 1][row] = v.y;
            As[c4 * 4 + 2][row] = v.z;
            As[c4 * 4 + 3][row] = v.w;
        }
        // B tiles: 32 rows x 16 float4/row = 512 float4; 2 per thread per matrix
#pragma unroll
        for (int j = 0; j < 2; j++) {
            int flat = tid + j * 256;
            int row = flat >> 4;
            int c4 = flat & 15;
            size_t off = (size_t)(kb + row) * F_DIM + nb + c4 * 4;
            *(float4*)&Bgs[row][c4 * 4] = *(const float4*)(wg + off);
            *(float4*)&Bus[row][c4 * 4] = *(const float4*)(wu + off);
        }
        __syncthreads();

#pragma unroll
        for (int kk = 0; kk < BK; kk++) {
            float a[8], bg[4], bu[4];
#pragma unroll
            for (int i = 0; i < 8; i++) a[i] = As[kk][ty * 8 + i];
#pragma unroll
            for (int j = 0; j < 4; j++) { bg[j] = Bgs[kk][tx * 4 + j]; bu[j] = Bus[kk][tx * 4 + j]; }
#pragma unroll
            for (int i = 0; i < 8; i++)
#pragma unroll
                for (int j = 0; j < 4; j++) {
                    accg[i][j] += a[i] * bg[j];
                    accu[i][j] += a[i] * bu[j];
                }
        }
        __syncthreads();
    }

    // epilogue: SiLU(gate) * up
#pragma unroll
    for (int i = 0; i < 8; i++) {
        int p = base + ty * 8 + i;
        if (p >= end) continue;
        float* hrow = g_h + (size_t)p * F_DIM + nb + tx * 4;
#pragma unroll
        for (int j = 0; j < 4; j++) {
            float g = accg[i][j];
            float s = 1.f / (1.f + expf(-g));
            hrow[j] = g * s * accu[i][j];
        }
    }
}

// ---------------- 4) down-proj GEMM: y[t,slot,:] = w * (h[p,:] @ Wd[e]) ----------------
__global__ void __launch_bounds__(256, 2)
down_kernel(const float* __restrict__ Wd) {
    int e = blockIdx.z;
    int base = g_off[e] + blockIdx.x * BM;
    int end  = g_off[e + 1];
    if (base >= end) return;
    int nb = blockIdx.y * BN;

    __shared__ float As[BK][BM + APAD];
    __shared__ float Bs[BK][BN];

    const float* wd = Wd + (size_t)e * F_DIM * D_DIM;

    int tid = threadIdx.x;
    int ty = tid >> 4;
    int tx = tid & 15;

    float acc[8][4];
#pragma unroll
    for (int i = 0; i < 8; i++)
#pragma unroll
        for (int j = 0; j < 4; j++) acc[i][j] = 0.f;

    for (int kb = 0; kb < F_DIM; kb += BK) {
#pragma unroll
        for (int j = 0; j < 4; j++) {
            int flat = tid + j * 256;
            int row = flat >> 3;
            int c4 = flat & 7;
            int p = base + row;
            float4 v = make_float4(0.f, 0.f, 0.f, 0.f);
            if (p < end)
                v = *(const float4*)(g_h + (size_t)p * F_DIM + kb + c4 * 4);
            As[c4 * 4 + 0][row] = v.x;
            As[c4 * 4 + 1][row] = v.y;
            As[c4 * 4 + 2][row] = v.z;
            As[c4 * 4 + 3][row] = v.w;
        }
#pragma unroll
        for (int j = 0; j < 2; j++) {
            int flat = tid + j * 256;
            int row = flat >> 4;
            int c4 = flat & 15;
            size_t off = (size_t)(kb + row) * D_DIM + nb + c4 * 4;
            *(float4*)&Bs[row][c4 * 4] = *(const float4*)(wd + off);
        }
        __syncthreads();

#pragma unroll
        for (int kk = 0; kk < BK; kk++) {
            float a[8], b[4];
#pragma unroll
            for (int i = 0; i < 8; i++) a[i] = As[kk][ty * 8 + i];
#pragma unroll
            for (int j = 0; j < 4; j++) b[j] = Bs[kk][tx * 4 + j];
#pragma unroll
            for (int i = 0; i < 8; i++)
#pragma unroll
                for (int j = 0; j < 4; j++) acc[i][j] += a[i] * b[j];
        }
        __syncthreads();
    }

#pragma unroll
    for (int i = 0; i < 8; i++) {
        int p = base + ty * 8 + i;
        if (p >= end) continue;
        int t = g_pair_tok[p];
        int slot = g_pair_slot[p];
        float w = g_pair_w[p];
        float* yrow = g_y + ((size_t)(t * 2 + slot)) * D_DIM + nb + tx * 4;
#pragma unroll
        for (int j = 0; j < 4; j++) yrow[j] = w * acc[i][j];
    }
}

// ---------------- 5) combine: out[t,:] = y[t,0,:] + y[t,1,:] ----------------
__global__ void combine_kernel(float* __restrict__ out) {
    int i = blockIdx.x * blockDim.x + threadIdx.x;  // 0 .. T*D-1
    if (i >= T_TOK * D_DIM) return;
    int t = i >> 10;
    int d = i & (D_DIM - 1);
    out[i] = g_y[((size_t)(t * 2) ) * D_DIM + d] + g_y[((size_t)(t * 2 + 1)) * D_DIM + d];
}

// ---------------- launch ----------------
extern "C" void kernel_launch(void* const* d_in, const int* in_sizes, int n_in,
                              void* d_out, int out_size) {
    const float* x  = (const float*)d_in[0];
    const float* wr = (const float*)d_in[1];
    const float* Wg = (const float*)d_in[2];
    const float* Wu = (const float*)d_in[3];
    const float* Wd = (const float*)d_in[4];
    float* out = (float*)d_out;

    router_kernel<<<T_TOK / 8, 256>>>(x, wr);
    assign_kernel<<<1, 256>>>();
    gateup_kernel<<<dim3(T_TOK / BM, F_DIM / BN, E_NUM), 256>>>(x, Wg, Wu);
    down_kernel<<<dim3(T_TOK / BM, D_DIM / BN, E_NUM), 256>>>(Wd);
    combine_kernel<<<(T_TOK * D_DIM + 255) / 256, 256>>>(out);
}

// round 4
// speedup vs baseline: 3.1324x; 3.1295x over previous
#include <cuda_runtime.h>
#include <math.h>
#include <stdint.h>

#define T_TOK 2048
#define D_DIM 1024
#define F_DIM 4096
#define E_NUM 8
#define NPAIR (T_TOK * 2)

#define BM 128
#define BN 128
#define BK 32
#define SA_STR 36      // A smem row stride (floats): bank = 4g+t, conflict-free
#define SB_STR 136     // B smem row stride (floats): bank = 8t+g, conflict-free
#define A_BYTES (BM * SA_STR * 4)       // 18432
#define B_BYTES (BK * SB_STR * 4)       // 17408
#define STAGE_BYTES (A_BYTES + B_BYTES) // 35840
#define SMEM_TOTAL (2 * STAGE_BYTES)    // 71680

// ---------------- scratch (device globals) ----------------
__device__ int   g_off[E_NUM + 1];
__device__ int   g_pair_tok[NPAIR];
__device__ int   g_pair_slot[NPAIR];
__device__ float g_pair_w[NPAIR];
__device__ int   g_tok_e[NPAIR];
__device__ float g_tok_w[NPAIR];
__device__ float g_gate[(size_t)NPAIR * F_DIM];  // 64 MB
__device__ float g_up[(size_t)NPAIR * F_DIM];    // 64 MB
__device__ float g_h[(size_t)NPAIR * F_DIM];     // 64 MB
__device__ float g_y[(size_t)NPAIR * D_DIM];     // 16 MB

// ---------------- PTX helpers (sm_103 baseline only; no 'a' features) ----------------
__device__ __forceinline__ uint32_t smem_u32(const void* p) {
    uint32_t a;
    asm("{ .reg .u64 t; cvta.to.shared.u64 t, %1; cvt.u32.u64 %0, t; }" : "=r"(a) : "l"(p));
    return a;
}
__device__ __forceinline__ void cp16(uint32_t dst, const void* src) {
    asm volatile("cp.async.cg.shared.global [%0], [%1], 16;" :: "r"(dst), "l"(src));
}
#define CP_COMMIT() asm volatile("cp.async.commit_group;" ::: "memory")
#define CP_WAIT(n)  asm volatile("cp.async.wait_group %0;" :: "n"(n) : "memory")

// load fp32 from smem, round-to-nearest to tf32 bits
__device__ __forceinline__ uint32_t ldtf(uint32_t addr) {
    float v;
    asm volatile("ld.shared.f32 %0, [%1];" : "=f"(v) : "r"(addr));
    uint32_t r;
    asm("cvt.rna.tf32.f32 %0, %1;" : "=r"(r) : "f"(v));
    return r;
}
__device__ __forceinline__ void mma8(float* d, uint32_t a0, uint32_t a1, uint32_t a2, uint32_t a3,
                                     uint32_t b0, uint32_t b1) {
    asm volatile(
        "mma.sync.aligned.m16n8k8.row.col.f32.tf32.tf32.f32 "
        "{%0,%1,%2,%3}, {%4,%5,%6,%7}, {%8,%9}, {%0,%1,%2,%3};"
        : "+f"(d[0]), "+f"(d[1]), "+f"(d[2]), "+f"(d[3])
        : "r"(a0), "r"(a1), "r"(a2), "r"(a3), "r"(b0), "r"(b1));
}

// ---------------- 1) router (exact fp32) ----------------
__global__ void router_kernel(const float* __restrict__ x, const float* __restrict__ wr) {
    int warp = threadIdx.x >> 5;
    int lane = threadIdx.x & 31;
    int t = blockIdx.x * 8 + warp;
    if (t >= T_TOK) return;

    float acc[E_NUM];
#pragma unroll
    for (int e = 0; e < E_NUM; e++) acc[e] = 0.f;

    const float* xr = x + (size_t)t * D_DIM;
    for (int d = lane; d < D_DIM; d += 32) {
        float xv = xr[d];
        const float4* w4 = (const float4*)(wr + (size_t)d * E_NUM);
        float4 w0 = w4[0];
        float4 w1 = w4[1];
        acc[0] += xv * w0.x; acc[1] += xv * w0.y;
        acc[2] += xv * w0.z; acc[3] += xv * w0.w;
        acc[4] += xv * w1.x; acc[5] += xv * w1.y;
        acc[6] += xv * w1.z; acc[7] += xv * w1.w;
    }
#pragma unroll
    for (int off = 16; off > 0; off >>= 1)
#pragma unroll
        for (int e = 0; e < E_NUM; e++)
            acc[e] += __shfl_xor_sync(0xFFFFFFFFu, acc[e], off);
    if (lane == 0) {
        int i1 = 0;
#pragma unroll
        for (int e = 1; e < E_NUM; e++) if (acc[e] > acc[i1]) i1 = e;
        int i2 = (i1 == 0) ? 1 : 0;
#pragma unroll
        for (int e = 0; e < E_NUM; e++)
            if (e != i1 && acc[e] > acc[i2]) i2 = e;
        float w1 = 1.f / (1.f + expf(acc[i2] - acc[i1]));
        g_tok_e[t * 2 + 0] = i1;
        g_tok_e[t * 2 + 1] = i2;
        g_tok_w[t * 2 + 0] = w1;
        g_tok_w[t * 2 + 1] = 1.f - w1;
    }
}

// ---------------- 2) per-expert lists ----------------
__global__ void assign_kernel() {
    __shared__ int s_cnt[E_NUM];
    __shared__ int s_fill[E_NUM];
    if (threadIdx.x < E_NUM) s_cnt[threadIdx.x] = 0;
    __syncthreads();
    for (int p = threadIdx.x; p < NPAIR; p += blockDim.x)
        atomicAdd(&s_cnt[g_tok_e[p]], 1);
    __syncthreads();
    if (threadIdx.x == 0) {
        int o = 0;
        for (int e = 0; e < E_NUM; e++) { g_off[e] = o; s_fill[e] = o; o += s_cnt[e]; }
        g_off[E_NUM] = o;
    }
    __syncthreads();
    for (int p = threadIdx.x; p < NPAIR; p += blockDim.x) {
        int e = g_tok_e[p];
        int pos = atomicAdd(&s_fill[e], 1);
        g_pair_tok[pos]  = p >> 1;
        g_pair_slot[pos] = p & 1;
        g_pair_w[pos]    = g_tok_w[p];
    }
}

// ---------------- shared GEMM compute core (tf32 mma.sync, warp tile 64x32) ----------------
struct Frag { float a[4][4][4]; };   // acc[mf][nf][4]

__device__ __forceinline__ void gemm_compute(uint32_t sA, uint32_t sB,
                                             int wm, int wn, int g, int t,
                                             float acc[4][4][4]) {
    uint32_t aBase = sA + (uint32_t)(((wm + g) * SA_STR + t) * 4);
    uint32_t bBase = sB + (uint32_t)((t * SB_STR + wn + g) * 4);
#pragma unroll
    for (int ks = 0; ks < 4; ks++) {
        uint32_t aK = aBase + ks * 8 * 4;
        uint32_t bK = bBase + ks * 8 * SB_STR * 4;
        uint32_t A0[4], A1[4], A2[4], A3[4];
#pragma unroll
        for (int mf = 0; mf < 4; mf++) {
            uint32_t ab = aK + mf * 16 * SA_STR * 4;
            A0[mf] = ldtf(ab);
            A1[mf] = ldtf(ab + 8 * SA_STR * 4);
            A2[mf] = ldtf(ab + 16);
            A3[mf] = ldtf(ab + 8 * SA_STR * 4 + 16);
        }
        uint32_t B0[4], B1[4];
#pragma unroll
        for (int nf = 0; nf < 4; nf++) {
            uint32_t bb = bK + nf * 8 * 4;
            B0[nf] = ldtf(bb);
            B1[nf] = ldtf(bb + 4 * SB_STR * 4);
        }
#pragma unroll
        for (int mf = 0; mf < 4; mf++)
#pragma unroll
            for (int nf = 0; nf < 4; nf++)
                mma8(acc[mf][nf], A0[mf], A1[mf], A2[mf], A3[mf], B0[nf], B1[nf]);
    }
}

// ---------------- 3) gate/up GEMM (grid.y: 0..31 = gate Nblk, 32..63 = up Nblk) ----------------
__global__ void __launch_bounds__(256)
gemm_gu(const float* __restrict__ x,
        const float* __restrict__ Wg,
        const float* __restrict__ Wu) {
    int e = blockIdx.z;
    int base = g_off[e] + blockIdx.x * BM;
    int end  = g_off[e + 1];
    if (base >= end) return;
    int mat = blockIdx.y >> 5;
    int nb  = (blockIdx.y & 31) * BN;
    const float* W = (mat ? Wu : Wg) + (size_t)e * D_DIM * F_DIM;
    float* out = mat ? g_up : g_gate;

    extern __shared__ char smem[];
    uint32_t s0 = smem_u32(smem);

    int tid = threadIdx.x, lane = tid & 31, wid = tid >> 5;
    int g = lane >> 2, t = lane & 3;
    int wm = (wid & 1) * 64, wn = (wid >> 1) * 32;

    // gathered A row pointers (clamped: invalid rows compute garbage, stores guarded)
    const float* aSrc[4];
#pragma unroll
    for (int i = 0; i < 4; i++) {
        int p = base + (tid >> 3) + i * 32;
        if (p > end - 1) p = end - 1;
        aSrc[i] = x + (size_t)g_pair_tok[p] * D_DIM;
    }
    int aj = tid & 7;

    float acc[4][4][4];
#pragma unroll
    for (int mf = 0; mf < 4; mf++)
#pragma unroll
        for (int nf = 0; nf < 4; nf++)
#pragma unroll
            for (int c = 0; c < 4; c++) acc[mf][nf][c] = 0.f;

    const int NC = D_DIM / BK;  // 32
    // prologue loads
    {
        uint32_t sA = s0, sB = s0 + A_BYTES;
#pragma unroll
        for (int i = 0; i < 4; i++)
            cp16(sA + (uint32_t)(((tid >> 3) + i * 32) * SA_STR * 4 + aj * 16),
                 aSrc[i] + aj * 4);
#pragma unroll
        for (int i = 0; i < 4; i++) {
            int kr = (tid >> 5) + i * 8;
            cp16(sB + (uint32_t)(kr * SB_STR * 4 + (tid & 31) * 16),
                 W + (size_t)kr * F_DIM + nb + (tid & 31) * 4);
        }
        CP_COMMIT();
    }

    for (int c = 0; c < NC; c++) {
        if (c + 1 < NC) {
            int kb = (c + 1) * BK;
            uint32_t sA = s0 + ((c + 1) & 1) * STAGE_BYTES;
            uint32_t sB = sA + A_BYTES;
#pragma unroll
            for (int i = 0; i < 4; i++)
                cp16(sA + (uint32_t)(((tid >> 3) + i * 32) * SA_STR * 4 + aj * 16),
                     aSrc[i] + kb + aj * 4);
#pragma unroll
            for (int i = 0; i < 4; i++) {
                int kr = (tid >> 5) + i * 8;
                cp16(sB + (uint32_t)(kr * SB_STR * 4 + (tid & 31) * 16),
                     W + (size_t)(kb + kr) * F_DIM + nb + (tid & 31) * 4);
            }
            CP_COMMIT();
            CP_WAIT(1);
        } else {
            CP_WAIT(0);
        }
        __syncthreads();
        uint32_t sA = s0 + (c & 1) * STAGE_BYTES;
        gemm_compute(sA, sA + A_BYTES, wm, wn, g, t, acc);
        __syncthreads();
    }

    // epilogue: raw GEMM result
#pragma unroll
    for (int mf = 0; mf < 4; mf++) {
        int p0 = base + wm + mf * 16 + g;
        int p1 = p0 + 8;
#pragma unroll
        for (int nf = 0; nf < 4; nf++) {
            int col = nb + wn + nf * 8 + 2 * t;
            if (p0 < end)
                *(float2*)(out + (size_t)p0 * F_DIM + col) = make_float2(acc[mf][nf][0], acc[mf][nf][1]);
            if (p1 < end)
                *(float2*)(out + (size_t)p1 * F_DIM + col) = make_float2(acc[mf][nf][2], acc[mf][nf][3]);
        }
    }
}

// ---------------- 4) silu combine: g_h = silu(g_gate) * g_up ----------------
__global__ void silu_kernel() {
    size_t i = (size_t)blockIdx.x * blockDim.x + threadIdx.x;   // float4 index
    float4 gv = ((const float4*)g_gate)[i];
    float4 uv = ((const float4*)g_up)[i];
    float4 r;
    r.x = gv.x / (1.f + expf(-gv.x)) * uv.x;
    r.y = gv.y / (1.f + expf(-gv.y)) * uv.y;
    r.z = gv.z / (1.f + expf(-gv.z)) * uv.z;
    r.w = gv.w / (1.f + expf(-gv.w)) * uv.w;
    ((float4*)g_h)[i] = r;
}

// ---------------- 5) down GEMM: g_y[tok*2+slot] = w * (g_h row @ Wd[e]) ----------------
__global__ void __launch_bounds__(256)
gemm_down(const float* __restrict__ Wd) {
    int e = blockIdx.z;
    int base = g_off[e] + blockIdx.x * BM;
    int end  = g_off[e + 1];
    if (base >= end) return;
    int nb = blockIdx.y * BN;
    const float* W = Wd + (size_t)e * F_DIM * D_DIM;

    extern __shared__ char smem[];
    uint32_t s0 = smem_u32(smem);

    int tid = threadIdx.x, lane = tid & 31, wid = tid >> 5;
    int g = lane >> 2, t = lane & 3;
    int wm = (wid & 1) * 64, wn = (wid >> 1) * 32;

    const float* aSrc[4];
#pragma unroll
    for (int i = 0; i < 4; i++) {
        int p = base + (tid >> 3) + i * 32;
        if (p > end - 1) p = end - 1;
        aSrc[i] = g_h + (size_t)p * F_DIM;
    }
    int aj = tid & 7;

    float acc[4][4][4];
#pragma unroll
    for (int mf = 0; mf < 4; mf++)
#pragma unroll
        for (int nf = 0; nf < 4; nf++)
#pragma unroll
            for (int c = 0; c < 4; c++) acc[mf][nf][c] = 0.f;

    const int NC = F_DIM / BK;  // 128
    {
        uint32_t sA = s0, sB = s0 + A_BYTES;
#pragma unroll
        for (int i = 0; i < 4; i++)
            cp16(sA + (uint32_t)(((tid >> 3) + i * 32) * SA_STR * 4 + aj * 16),
                 aSrc[i] + aj * 4);
#pragma unroll
        for (int i = 0; i < 4; i++) {
            int kr = (tid >> 5) + i * 8;
            cp16(sB + (uint32_t)(kr * SB_STR * 4 + (tid & 31) * 16),
                 W + (size_t)kr * D_DIM + nb + (tid & 31) * 4);
        }
        CP_COMMIT();
    }

    for (int c = 0; c < NC; c++) {
        if (c + 1 < NC) {
            int kb = (c + 1) * BK;
            uint32_t sA = s0 + ((c + 1) & 1) * STAGE_BYTES;
            uint32_t sB = sA + A_BYTES;
#pragma unroll
            for (int i = 0; i < 4; i++)
                cp16(sA + (uint32_t)(((tid >> 3) + i * 32) * SA_STR * 4 + aj * 16),
                     aSrc[i] + kb + aj * 4);
#pragma unroll
            for (int i = 0; i < 4; i++) {
                int kr = (tid >> 5) + i * 8;
                cp16(sB + (uint32_t)(kr * SB_STR * 4 + (tid & 31) * 16),
                     W + (size_t)(kb + kr) * D_DIM + nb + (tid & 31) * 4);
            }
            CP_COMMIT();
            CP_WAIT(1);
        } else {
            CP_WAIT(0);
        }
        __syncthreads();
        uint32_t sA = s0 + (c & 1) * STAGE_BYTES;
        gemm_compute(sA, sA + A_BYTES, wm, wn, g, t, acc);
        __syncthreads();
    }

#pragma unroll
    for (int mf = 0; mf < 4; mf++) {
        int p0 = base + wm + mf * 16 + g;
        int p1 = p0 + 8;
#pragma unroll
        for (int nf = 0; nf < 4; nf++) {
            int col = nb + wn + nf * 8 + 2 * t;
            if (p0 < end) {
                float w = g_pair_w[p0];
                size_t row = (size_t)(g_pair_tok[p0] * 2 + g_pair_slot[p0]);
                *(float2*)(g_y + row * D_DIM + col) =
                    make_float2(w * acc[mf][nf][0], w * acc[mf][nf][1]);
            }
            if (p1 < end) {
                float w = g_pair_w[p1];
                size_t row = (size_t)(g_pair_tok[p1] * 2 + g_pair_slot[p1]);
                *(float2*)(g_y + row * D_DIM + col) =
                    make_float2(w * acc[mf][nf][2], w * acc[mf][nf][3]);
            }
        }
    }
}

// ---------------- 6) combine ----------------
__global__ void combine_kernel(float* __restrict__ out) {
    int i = blockIdx.x * blockDim.x + threadIdx.x;
    if (i >= T_TOK * D_DIM) return;
    int t = i >> 10;
    int d = i & (D_DIM - 1);
    out[i] = g_y[((size_t)(t * 2)) * D_DIM + d] + g_y[((size_t)(t * 2 + 1)) * D_DIM + d];
}

// ---------------- launch ----------------
extern "C" void kernel_launch(void* const* d_in, const int* in_sizes, int n_in,
                              void* d_out, int out_size) {
    const float* x  = (const float*)d_in[0];
    const float* wr = (const float*)d_in[1];
    const float* Wg = (const float*)d_in[2];
    const float* Wu = (const float*)d_in[3];
    const float* Wd = (const float*)d_in[4];
    float* out = (float*)d_out;

    cudaFuncSetAttribute(gemm_gu,   cudaFuncAttributeMaxDynamicSharedMemorySize, SMEM_TOTAL);
    cudaFuncSetAttribute(gemm_down, cudaFuncAttributeMaxDynamicSharedMemorySize, SMEM_TOTAL);

    router_kernel<<<T_TOK / 8, 256>>>(x, wr);
    assign_kernel<<<1, 256>>>();
    gemm_gu<<<dim3(NPAIR / BM, 64, E_NUM), 256, SMEM_TOTAL>>>(x, Wg, Wu);
    silu_kernel<<<(NPAIR * (F_DIM / 4)) / 256, 256>>>();
    gemm_down<<<dim3(NPAIR / BM, D_DIM / BN, E_NUM), 256, SMEM_TOTAL>>>(Wd);
    combine_kernel<<<(T_TOK * D_DIM + 255) / 256, 256>>>(out);
}